// round 13
// baseline (speedup 1.0000x reference)
#include <cuda_runtime.h>
#include <math.h>

#define NN 100000
#define NE 1600000
#define NG 64
#define F1 100
#define F2 200

// ---------------- scratch (static device globals; no allocation) ----------
__device__ float2 g_pack[NN];          // (deg_sum, deg_count) packed for v2 red
__device__ float  g_dinv[NN];          // rsqrt(deg)
__device__ int    g_cdeg[NN];          // in-degree counts (for CSR)
__device__ int    g_offs[NN + 1];      // CSR offsets
__device__ int    g_fill[NN];          // CSR fill cursors
__device__ int    g_bsum[128];         // scan block sums
__device__ float2 g_csr[NE];           // (row as int bits, norm)
__device__ float  g_h1[NN * F1];       // silu((A@x) @ W1 + b1)
__device__ float  g_agg1[NN * F1];     // A_norm @ h1
__device__ float  g_sums[NG * F2];     // pooled sums
__device__ float  g_cnt[NG];           // pooled counts

__device__ __forceinline__ float silu(float v) {
    return v / (1.0f + __expf(-v));
}

__device__ __forceinline__ unsigned f2tf32(float v) {
    unsigned r;
    asm("cvt.rna.tf32.f32 %0, %1;" : "=r"(r) : "f"(v));
    return r;
}

__device__ __forceinline__ void split_tf32(float v, unsigned& hi, unsigned& lo) {
    hi = f2tf32(v);
    lo = f2tf32(v - __uint_as_float(hi));
}

__device__ __forceinline__ void mma_tf32(float& d0, float& d1, float& d2, float& d3,
                                         unsigned a0, unsigned a1, unsigned a2, unsigned a3,
                                         unsigned b0, unsigned b1) {
    asm volatile("mma.sync.aligned.m16n8k8.row.col.f32.tf32.tf32.f32 "
                 "{%0,%1,%2,%3}, {%4,%5,%6,%7}, {%8,%9}, {%0,%1,%2,%3};"
                 : "+f"(d0), "+f"(d1), "+f"(d2), "+f"(d3)
                 : "r"(a0), "r"(a1), "r"(a2), "r"(a3), "r"(b0), "r"(b1));
}

__device__ __forceinline__ void red_add_v2(float2* p, float a, float b) {
    asm volatile("red.global.add.v2.f32 [%0], {%1,%2};"
                 :: "l"(p), "f"(a), "f"(b) : "memory");
}

// ---------------- K1: init pack (self-loop: deg=1, cnt=0), zero pooled ----
__global__ void k_init() {
    int i = blockIdx.x * blockDim.x + threadIdx.x;
    if (i < NN) g_pack[i] = make_float2(1.0f, 0.0f);
    if (i < NG * F2) g_sums[i] = 0.0f;
    if (i < NG) g_cnt[i] = 0.0f;
}

// ---------------- K2: packed deg/count reduction (1 atomic per edge) ------
__global__ void k_deg(const int* __restrict__ ei, const float* __restrict__ w) {
    int e = blockIdx.x * blockDim.x + threadIdx.x;
    if (e >= NE) return;
    int col = ei[NE + e];
    red_add_v2(&g_pack[col], w[e], 1.0f);
}

// ---------------- K3: dinv = rsqrt(deg); cdeg; graph counts ---------------
__global__ void k_dinv(const int* __restrict__ batch) {
    int n = blockIdx.x * blockDim.x + threadIdx.x;
    bool valid = n < NN;
    if (valid) {
        float2 p = g_pack[n];
        g_dinv[n] = rsqrtf(p.x);          // deg >= 1 (self loop)
        g_cdeg[n] = (int)p.y;             // counts exact in float
    }
    int g = valid ? batch[n] : -1;
    unsigned m = __match_any_sync(0xffffffffu, g);
    int lane = threadIdx.x & 31;
    int leader = __ffs(m) - 1;
    if (valid && lane == leader)
        atomicAdd(&g_cnt[g], (float)__popc(m));
}

// ---------------- scan: exclusive prefix sum of cdeg -> offs --------------
__global__ void k_scan1() {
    __shared__ int warp_s[8];
    int b = blockIdx.x, t = threadIdx.x;
    int base = b * 1024 + t * 4;
    int v0 = 0, v1 = 0, v2 = 0, v3 = 0;
    if (base + 0 < NN) v0 = g_cdeg[base + 0];
    if (base + 1 < NN) v1 = g_cdeg[base + 1];
    if (base + 2 < NN) v2 = g_cdeg[base + 2];
    if (base + 3 < NN) v3 = g_cdeg[base + 3];
    int s = v0 + v1 + v2 + v3;
    int lane = t & 31, wid = t >> 5;
    int ps = s;
#pragma unroll
    for (int o = 1; o < 32; o <<= 1) {
        int u = __shfl_up_sync(0xffffffffu, ps, o);
        if (lane >= o) ps += u;
    }
    if (lane == 31) warp_s[wid] = ps;
    __syncthreads();
    if (t < 8) {
        int ws = warp_s[t];
        int pw = ws;
#pragma unroll
        for (int o = 1; o < 8; o <<= 1) {
            int u = __shfl_up_sync(0xffu, pw, o);
            if (t >= o) pw += u;
        }
        warp_s[t] = pw - ws;
    }
    __syncthreads();
    int ex = ps - s + warp_s[wid];
    int run = ex;
    if (base + 0 < NN) g_offs[base + 0] = run; run += v0;
    if (base + 1 < NN) g_offs[base + 1] = run; run += v1;
    if (base + 2 < NN) g_offs[base + 2] = run; run += v2;
    if (base + 3 < NN) g_offs[base + 3] = run;
    if (t == 255) g_bsum[b] = ex + s;
}

__global__ void k_scan2() {
    __shared__ int sh[4];
    int t = threadIdx.x;
    int v = (t < 98) ? g_bsum[t] : 0;
    int lane = t & 31, wid = t >> 5;
    int ps = v;
#pragma unroll
    for (int o = 1; o < 32; o <<= 1) {
        int u = __shfl_up_sync(0xffffffffu, ps, o);
        if (lane >= o) ps += u;
    }
    if (lane == 31) sh[wid] = ps;
    __syncthreads();
    if (t < 4) {
        int ws = sh[t];
        int pw = ws;
#pragma unroll
        for (int o = 1; o < 4; o <<= 1) {
            int u = __shfl_up_sync(0xfu, pw, o);
            if (t >= o) pw += u;
        }
        sh[t] = pw - ws;
    }
    __syncthreads();
    if (t < 98) g_bsum[t] = ps - v + sh[wid];
}

__global__ void k_scan3() {
    int i = blockIdx.x * blockDim.x + threadIdx.x;
    if (i < NN) {
        int o = g_offs[i] + g_bsum[i >> 10];
        g_offs[i] = o;
        g_fill[i] = o;
    }
    if (i == 0) g_offs[NN] = NE;
}

// ---------------- K5: build CSR (row, norm) per target node ---------------
__global__ void k_build(const int* __restrict__ ei, const float* __restrict__ w) {
    int e = blockIdx.x * blockDim.x + threadIdx.x;
    if (e >= NE) return;
    int row = ei[e];
    int col = ei[NE + e];
    float nm = g_dinv[row] * w[e] * g_dinv[col];
    int pos = atomicAdd(&g_fill[col], 1);
    g_csr[pos] = make_float2(__int_as_float(row), nm);
}

// ---------------- K6: fused aggX + h1 -------------------------------------
__global__ void k_aggXh1(const float* __restrict__ x,
                         const float* __restrict__ W1, const float* __restrict__ b1) {
    __shared__ float sW[4 * F1];
    for (int t = threadIdx.x; t < 4 * F1; t += blockDim.x)
        sW[t] = (t < 3 * F1) ? W1[t] : b1[t - 3 * F1];
    __syncthreads();
    int n = blockIdx.x * blockDim.x + threadIdx.x;
    if (n >= NN) return;
    float di = g_dinv[n];
    float s = di * di;
    float a0 = s * x[3 * n + 0];
    float a1 = s * x[3 * n + 1];
    float a2 = s * x[3 * n + 2];
    int beg = g_offs[n], end = g_offs[n + 1];
    int j = beg;
    for (; j + 4 <= end; j += 4) {
        float2 c0 = g_csr[j + 0];
        float2 c1 = g_csr[j + 1];
        float2 c2 = g_csr[j + 2];
        float2 c3 = g_csr[j + 3];
        int r0 = __float_as_int(c0.x);
        int r1 = __float_as_int(c1.x);
        int r2 = __float_as_int(c2.x);
        int r3 = __float_as_int(c3.x);
        float x00 = x[3 * r0 + 0], x01 = x[3 * r0 + 1], x02 = x[3 * r0 + 2];
        float x10 = x[3 * r1 + 0], x11 = x[3 * r1 + 1], x12 = x[3 * r1 + 2];
        float x20 = x[3 * r2 + 0], x21 = x[3 * r2 + 1], x22 = x[3 * r2 + 2];
        float x30 = x[3 * r3 + 0], x31 = x[3 * r3 + 1], x32 = x[3 * r3 + 2];
        a0 = fmaf(c0.y, x00, a0); a1 = fmaf(c0.y, x01, a1); a2 = fmaf(c0.y, x02, a2);
        a0 = fmaf(c1.y, x10, a0); a1 = fmaf(c1.y, x11, a1); a2 = fmaf(c1.y, x12, a2);
        a0 = fmaf(c2.y, x20, a0); a1 = fmaf(c2.y, x21, a1); a2 = fmaf(c2.y, x22, a2);
        a0 = fmaf(c3.y, x30, a0); a1 = fmaf(c3.y, x31, a1); a2 = fmaf(c3.y, x32, a2);
    }
    for (; j < end; j++) {
        float2 c = g_csr[j];
        int r = __float_as_int(c.x);
        a0 = fmaf(c.y, x[3 * r + 0], a0);
        a1 = fmaf(c.y, x[3 * r + 1], a1);
        a2 = fmaf(c.y, x[3 * r + 2], a2);
    }
#pragma unroll
    for (int c4 = 0; c4 < 25; c4++) {
        float4 o;
#pragma unroll
        for (int jj = 0; jj < 4; jj++) {
            int c = c4 * 4 + jj;
            float v = fmaf(a0, sW[c], fmaf(a1, sW[F1 + c], fmaf(a2, sW[2 * F1 + c], sW[3 * F1 + c])));
            (&o.x)[jj] = silu(v);
        }
        *(float4*)(g_h1 + (long)n * F1 + c4 * 4) = o;
    }
}

// ---------------- K7: agg1[n] = s*h1[n] + sum nrm*h1[row] (warp/node) -----
__global__ void k_agg1() {
    int n = (blockIdx.x * blockDim.x + threadIdx.x) >> 5;
    int lane = threadIdx.x & 31;
    if (n >= NN) return;
    bool act = lane < 25;
    int beg = g_offs[n], end = g_offs[n + 1];
    float di = g_dinv[n];
    float s = di * di;
    float4 acc = make_float4(0.f, 0.f, 0.f, 0.f);
    if (act) {
        float4 h = *(const float4*)(g_h1 + (long)n * F1 + lane * 4);
        acc.x = s * h.x; acc.y = s * h.y; acc.z = s * h.z; acc.w = s * h.w;
    }
    int j = beg;
    for (; j + 8 <= end; j += 8) {
        float2 cc[8];
        int rr[8];
#pragma unroll
        for (int q = 0; q < 8; q++) {
            cc[q] = g_csr[j + q];
            rr[q] = __float_as_int(cc[q].x);
        }
        if (act) {
            float4 hh[8];
#pragma unroll
            for (int q = 0; q < 8; q++)
                hh[q] = *(const float4*)(g_h1 + (long)rr[q] * F1 + lane * 4);
#pragma unroll
            for (int q = 0; q < 8; q++) {
                acc.x = fmaf(cc[q].y, hh[q].x, acc.x);
                acc.y = fmaf(cc[q].y, hh[q].y, acc.y);
                acc.z = fmaf(cc[q].y, hh[q].z, acc.z);
                acc.w = fmaf(cc[q].y, hh[q].w, acc.w);
            }
        }
    }
    for (; j + 2 <= end; j += 2) {
        float2 c0 = g_csr[j];
        float2 c1 = g_csr[j + 1];
        int r0 = __float_as_int(c0.x);
        int r1 = __float_as_int(c1.x);
        if (act) {
            float4 h0 = *(const float4*)(g_h1 + (long)r0 * F1 + lane * 4);
            float4 h1v = *(const float4*)(g_h1 + (long)r1 * F1 + lane * 4);
            acc.x = fmaf(c0.y, h0.x, acc.x); acc.y = fmaf(c0.y, h0.y, acc.y);
            acc.z = fmaf(c0.y, h0.z, acc.z); acc.w = fmaf(c0.y, h0.w, acc.w);
            acc.x = fmaf(c1.y, h1v.x, acc.x); acc.y = fmaf(c1.y, h1v.y, acc.y);
            acc.z = fmaf(c1.y, h1v.z, acc.z); acc.w = fmaf(c1.y, h1v.w, acc.w);
        }
    }
    if (j < end) {
        float2 c0 = g_csr[j];
        int r0 = __float_as_int(c0.x);
        if (act) {
            float4 h0 = *(const float4*)(g_h1 + (long)r0 * F1 + lane * 4);
            acc.x = fmaf(c0.y, h0.x, acc.x); acc.y = fmaf(c0.y, h0.y, acc.y);
            acc.z = fmaf(c0.y, h0.z, acc.z); acc.w = fmaf(c0.y, h0.w, acc.w);
        }
    }
    if (act)
        *(float4*)(g_agg1 + (long)n * F1 + lane * 4) = acc;
}

// ---------------- K8: 3xTF32 GEMM, A staged once, reg-pool epilogue -------
// grid = ceil(NN/64) (1-D), 128 threads (4 warps, one m16 band each).
// A-tile loaded once into smem; internal loop over 5 col-blocks of 40.
// Pooling done from mma accumulators: shfl_xor butterfly over the 8 r-lanes
// when all 16 warp rows share one graph (common), else per-lane atomics.
#define BM 64
#define BN 40
#define KP 104
#define ASTRIDE 108

__global__ void k_gemm2(const float* __restrict__ W2, const float* __restrict__ b2,
                        const int* __restrict__ batch) {
    __shared__ float As[BM * ASTRIDE];   // [m][k] fp32 (lives whole kernel)
    __shared__ float Bs[KP * BN];        // [k][c] fp32 (per col-block)
    __shared__ int sBatch[BM];
    int tid = threadIdx.x;
    int lane = tid & 31;
    int wid = tid >> 5;
    int n0 = blockIdx.x * BM;

    // load A tile once
    for (int t = tid; t < BM * 25; t += 128) {
        int m = t / 25, k4 = t % 25;
        int n = n0 + m;
        float4 v = make_float4(0.f, 0.f, 0.f, 0.f);
        if (n < NN) v = *(const float4*)(g_agg1 + (long)n * F1 + k4 * 4);
        *(float4*)(As + m * ASTRIDE + k4 * 4) = v;
    }
    for (int t = tid; t < BM * 8; t += 128)
        As[(t >> 3) * ASTRIDE + 100 + (t & 7)] = 0.f;
    // zero K padding rows of Bs once (never overwritten by col-block loads)
    for (int t = tid; t < 4 * BN; t += 128)
        Bs[(100 + t / BN) * BN + (t % BN)] = 0.f;
    if (tid < BM) {
        int n = n0 + tid;
        sBatch[tid] = (n < NN) ? batch[n] : -1;
    }
    __syncthreads();

    int base = wid * 16;
    int r = lane >> 2;
    int c = lane & 3;

    // per-warp graph uniformity over its 16 rows
    int g0 = sBatch[base + r];
    int g1 = sBatch[base + r + 8];
    int gref = __shfl_sync(0xffffffffu, g0, 0);
    bool uni = __all_sync(0xffffffffu, g0 == gref && g1 == gref) && (gref >= 0);

#pragma unroll 1
    for (int cbi = 0; cbi < 5; cbi++) {
        int cb = cbi * BN;
        // load Bs for this col-block (W2 80KB, L2-hot)
        for (int t = tid; t < F1 * 10; t += 128) {
            int k = t / 10, c4 = t % 10;
            *(float4*)(Bs + k * BN + c4 * 4) = *(const float4*)(W2 + k * F2 + cb + c4 * 4);
        }
        __syncthreads();

        float acc[5][4] = {};
#pragma unroll
        for (int ks = 0; ks < 13; ks++) {
            int kb = ks * 8;
            float fa0 = As[(base + r) * ASTRIDE + kb + c];
            float fa1 = As[(base + r + 8) * ASTRIDE + kb + c];
            float fa2 = As[(base + r) * ASTRIDE + kb + c + 4];
            float fa3 = As[(base + r + 8) * ASTRIDE + kb + c + 4];
            unsigned ah0, al0, ah1, al1, ah2, al2, ah3, al3;
            split_tf32(fa0, ah0, al0);
            split_tf32(fa1, ah1, al1);
            split_tf32(fa2, ah2, al2);
            split_tf32(fa3, ah3, al3);
#pragma unroll
            for (int t = 0; t < 5; t++) {
                float fb0 = Bs[(kb + c) * BN + t * 8 + r];
                float fb1 = Bs[(kb + 4 + c) * BN + t * 8 + r];
                unsigned bh0, bl0, bh1, bl1;
                split_tf32(fb0, bh0, bl0);
                split_tf32(fb1, bh1, bl1);
                mma_tf32(acc[t][0], acc[t][1], acc[t][2], acc[t][3],
                         ah0, ah1, ah2, ah3, bl0, bl1);
                mma_tf32(acc[t][0], acc[t][1], acc[t][2], acc[t][3],
                         al0, al1, al2, al3, bh0, bh1);
                mma_tf32(acc[t][0], acc[t][1], acc[t][2], acc[t][3],
                         ah0, ah1, ah2, ah3, bh0, bh1);
            }
        }

        // epilogue: silu + pool straight from registers
#pragma unroll
        for (int t = 0; t < 5; t++) {
            int col = cb + t * 8 + c * 2;
            float bx = b2[col];
            float by = b2[col + 1];
            float v00 = silu(acc[t][0] + bx);   // (base+r,   col)
            float v01 = silu(acc[t][1] + by);   // (base+r,   col+1)
            float v10 = silu(acc[t][2] + bx);   // (base+r+8, col)
            float v11 = silu(acc[t][3] + by);   // (base+r+8, col+1)
            if (uni) {
                float s0 = v00 + v10;
                float s1 = v01 + v11;
                s0 += __shfl_xor_sync(0xffffffffu, s0, 4);
                s0 += __shfl_xor_sync(0xffffffffu, s0, 8);
                s0 += __shfl_xor_sync(0xffffffffu, s0, 16);
                s1 += __shfl_xor_sync(0xffffffffu, s1, 4);
                s1 += __shfl_xor_sync(0xffffffffu, s1, 8);
                s1 += __shfl_xor_sync(0xffffffffu, s1, 16);
                if (lane < 4) {
                    atomicAdd(&g_sums[gref * F2 + col], s0);
                    atomicAdd(&g_sums[gref * F2 + col + 1], s1);
                }
            } else {
                if (g0 >= 0) {
                    atomicAdd(&g_sums[g0 * F2 + col], v00);
                    atomicAdd(&g_sums[g0 * F2 + col + 1], v01);
                }
                if (g1 >= 0) {
                    atomicAdd(&g_sums[g1 * F2 + col], v10);
                    atomicAdd(&g_sums[g1 * F2 + col + 1], v11);
                }
            }
        }
        __syncthreads();   // Bs reuse guard for next col-block
    }
}

// ---------------- K9: head: silu(pooled@Wl1+bl1)@Wl2+bl2 ------------------
__global__ void k_head(const float* __restrict__ Wl1, const float* __restrict__ bl1,
                       const float* __restrict__ Wl2, const float* __restrict__ bl2,
                       float* __restrict__ out) {
    __shared__ float sp[F2];
    __shared__ float sh[F1];
    int g = blockIdx.x;
    int tid = threadIdx.x;
    float cnt = fmaxf(g_cnt[g], 1.0f);
    for (int c = tid; c < F2; c += blockDim.x)
        sp[c] = g_sums[g * F2 + c] / cnt;
    __syncthreads();
    if (tid < F1) {
        float acc = bl1[tid];
        for (int c = 0; c < F2; c++)
            acc = fmaf(sp[c], Wl1[c * F1 + tid], acc);
        sh[tid] = silu(acc);
    }
    __syncthreads();
    if (tid == 0) {
        float s = bl2[0];
        for (int j = 0; j < F1; j++)
            s = fmaf(sh[j], Wl2[j], s);
        out[g] = s;
    }
}

// ---------------- launch ---------------------------------------------------
extern "C" void kernel_launch(void* const* d_in, const int* in_sizes, int n_in,
                              void* d_out, int out_size) {
    const float* x   = (const float*)d_in[0];
    const float* ea  = (const float*)d_in[1];
    const float* W1  = (const float*)d_in[2];
    const float* b1  = (const float*)d_in[3];
    const float* W2  = (const float*)d_in[4];
    const float* b2  = (const float*)d_in[5];
    const float* Wl1 = (const float*)d_in[6];
    const float* bl1 = (const float*)d_in[7];
    const float* Wl2 = (const float*)d_in[8];
    const float* bl2 = (const float*)d_in[9];
    const int*   ei  = (const int*)d_in[10];
    const int*   bat = (const int*)d_in[11];
    float* out = (float*)d_out;

    k_init<<<(NN + 255) / 256, 256>>>();
    k_deg<<<(NE + 255) / 256, 256>>>(ei, ea);
    k_dinv<<<(NN + 255) / 256, 256>>>(bat);
    k_scan1<<<98, 256>>>();
    k_scan2<<<1, 128>>>();
    k_scan3<<<(NN + 255) / 256, 256>>>();
    k_build<<<(NE + 255) / 256, 256>>>(ei, ea);
    k_aggXh1<<<(NN + 255) / 256, 256>>>(x, W1, b1);
    k_agg1<<<(NN * 32 + 255) / 256, 256>>>();
    k_gemm2<<<(NN + BM - 1) / BM, 128>>>(W2, b2, bat);
    k_head<<<NG, 128>>>(Wl1, bl1, Wl2, bl2, out);
}

// round 14
// speedup vs baseline: 1.0021x; 1.0021x over previous
#include <cuda_runtime.h>
#include <math.h>

#define NN 100000
#define NE 1600000
#define NG 64
#define F1 100
#define F2 200

// ---------------- scratch (static device globals; no allocation) ----------
__device__ float2 g_pack[NN];          // (deg_sum, deg_count) packed for v2 red
__device__ float  g_dinv[NN];          // rsqrt(deg)
__device__ int    g_cdeg[NN];          // in-degree counts (for CSR)
__device__ int    g_offs[NN + 1];      // CSR offsets
__device__ int    g_fill[NN];          // CSR fill cursors
__device__ int    g_bsum[128];         // scan block sums
__device__ float2 g_csr[NE];           // (row as int bits, norm)
__device__ float  g_h1[NN * F1];       // silu((A@x) @ W1 + b1)
__device__ float  g_agg1[NN * F1];     // A_norm @ h1
__device__ float  g_sums[NG * F2];     // pooled sums
__device__ float  g_cnt[NG];           // pooled counts

__device__ __forceinline__ float silu(float v) {
    return v / (1.0f + __expf(-v));
}

__device__ __forceinline__ unsigned f2tf32(float v) {
    unsigned r;
    asm("cvt.rna.tf32.f32 %0, %1;" : "=r"(r) : "f"(v));
    return r;
}

__device__ __forceinline__ void split_tf32(float v, unsigned& hi, unsigned& lo) {
    hi = f2tf32(v);
    lo = f2tf32(v - __uint_as_float(hi));
}

__device__ __forceinline__ void mma_tf32(float& d0, float& d1, float& d2, float& d3,
                                         unsigned a0, unsigned a1, unsigned a2, unsigned a3,
                                         unsigned b0, unsigned b1) {
    asm volatile("mma.sync.aligned.m16n8k8.row.col.f32.tf32.tf32.f32 "
                 "{%0,%1,%2,%3}, {%4,%5,%6,%7}, {%8,%9}, {%0,%1,%2,%3};"
                 : "+f"(d0), "+f"(d1), "+f"(d2), "+f"(d3)
                 : "r"(a0), "r"(a1), "r"(a2), "r"(a3), "r"(b0), "r"(b1));
}

__device__ __forceinline__ void red_add_v2(float2* p, float a, float b) {
    asm volatile("red.global.add.v2.f32 [%0], {%1,%2};"
                 :: "l"(p), "f"(a), "f"(b) : "memory");
}

// ---------------- K1: init pack (self-loop: deg=1, cnt=0), zero pooled ----
__global__ void k_init() {
    int i = blockIdx.x * blockDim.x + threadIdx.x;
    if (i < NN) g_pack[i] = make_float2(1.0f, 0.0f);
    if (i < NG * F2) g_sums[i] = 0.0f;
    if (i < NG) g_cnt[i] = 0.0f;
}

// ---------------- K2: packed deg/count reduction (1 atomic per edge) ------
__global__ void k_deg(const int* __restrict__ ei, const float* __restrict__ w) {
    int e = blockIdx.x * blockDim.x + threadIdx.x;
    if (e >= NE) return;
    int col = ei[NE + e];
    red_add_v2(&g_pack[col], w[e], 1.0f);
}

// ---------------- K3: dinv = rsqrt(deg); cdeg; graph counts ---------------
__global__ void k_dinv(const int* __restrict__ batch) {
    int n = blockIdx.x * blockDim.x + threadIdx.x;
    bool valid = n < NN;
    if (valid) {
        float2 p = g_pack[n];
        g_dinv[n] = rsqrtf(p.x);          // deg >= 1 (self loop)
        g_cdeg[n] = (int)p.y;             // counts exact in float
    }
    int g = valid ? batch[n] : -1;
    unsigned m = __match_any_sync(0xffffffffu, g);
    int lane = threadIdx.x & 31;
    int leader = __ffs(m) - 1;
    if (valid && lane == leader)
        atomicAdd(&g_cnt[g], (float)__popc(m));
}

// ---------------- scan: exclusive prefix sum of cdeg -> offs --------------
__global__ void k_scan1() {
    __shared__ int warp_s[8];
    int b = blockIdx.x, t = threadIdx.x;
    int base = b * 1024 + t * 4;
    int v0 = 0, v1 = 0, v2 = 0, v3 = 0;
    if (base + 0 < NN) v0 = g_cdeg[base + 0];
    if (base + 1 < NN) v1 = g_cdeg[base + 1];
    if (base + 2 < NN) v2 = g_cdeg[base + 2];
    if (base + 3 < NN) v3 = g_cdeg[base + 3];
    int s = v0 + v1 + v2 + v3;
    int lane = t & 31, wid = t >> 5;
    int ps = s;
#pragma unroll
    for (int o = 1; o < 32; o <<= 1) {
        int u = __shfl_up_sync(0xffffffffu, ps, o);
        if (lane >= o) ps += u;
    }
    if (lane == 31) warp_s[wid] = ps;
    __syncthreads();
    if (t < 8) {
        int ws = warp_s[t];
        int pw = ws;
#pragma unroll
        for (int o = 1; o < 8; o <<= 1) {
            int u = __shfl_up_sync(0xffu, pw, o);
            if (t >= o) pw += u;
        }
        warp_s[t] = pw - ws;
    }
    __syncthreads();
    int ex = ps - s + warp_s[wid];
    int run = ex;
    if (base + 0 < NN) g_offs[base + 0] = run; run += v0;
    if (base + 1 < NN) g_offs[base + 1] = run; run += v1;
    if (base + 2 < NN) g_offs[base + 2] = run; run += v2;
    if (base + 3 < NN) g_offs[base + 3] = run;
    if (t == 255) g_bsum[b] = ex + s;
}

__global__ void k_scan2() {
    __shared__ int sh[4];
    int t = threadIdx.x;
    int v = (t < 98) ? g_bsum[t] : 0;
    int lane = t & 31, wid = t >> 5;
    int ps = v;
#pragma unroll
    for (int o = 1; o < 32; o <<= 1) {
        int u = __shfl_up_sync(0xffffffffu, ps, o);
        if (lane >= o) ps += u;
    }
    if (lane == 31) sh[wid] = ps;
    __syncthreads();
    if (t < 4) {
        int ws = sh[t];
        int pw = ws;
#pragma unroll
        for (int o = 1; o < 4; o <<= 1) {
            int u = __shfl_up_sync(0xfu, pw, o);
            if (t >= o) pw += u;
        }
        sh[t] = pw - ws;
    }
    __syncthreads();
    if (t < 98) g_bsum[t] = ps - v + sh[wid];
}

__global__ void k_scan3() {
    int i = blockIdx.x * blockDim.x + threadIdx.x;
    if (i < NN) {
        int o = g_offs[i] + g_bsum[i >> 10];
        g_offs[i] = o;
        g_fill[i] = o;
    }
    if (i == 0) g_offs[NN] = NE;
}

// ---------------- K5: build CSR (row, norm) per target node ---------------
__global__ void k_build(const int* __restrict__ ei, const float* __restrict__ w) {
    int e = blockIdx.x * blockDim.x + threadIdx.x;
    if (e >= NE) return;
    int row = ei[e];
    int col = ei[NE + e];
    float nm = g_dinv[row] * w[e] * g_dinv[col];
    int pos = atomicAdd(&g_fill[col], 1);
    g_csr[pos] = make_float2(__int_as_float(row), nm);
}

// ---------------- K6: fused aggX + h1 -------------------------------------
__global__ void k_aggXh1(const float* __restrict__ x,
                         const float* __restrict__ W1, const float* __restrict__ b1) {
    __shared__ float sW[4 * F1];
    for (int t = threadIdx.x; t < 4 * F1; t += blockDim.x)
        sW[t] = (t < 3 * F1) ? W1[t] : b1[t - 3 * F1];
    __syncthreads();
    int n = blockIdx.x * blockDim.x + threadIdx.x;
    if (n >= NN) return;
    float di = g_dinv[n];
    float s = di * di;
    float a0 = s * x[3 * n + 0];
    float a1 = s * x[3 * n + 1];
    float a2 = s * x[3 * n + 2];
    int beg = g_offs[n], end = g_offs[n + 1];
    int j = beg;
    for (; j + 4 <= end; j += 4) {
        float2 c0 = g_csr[j + 0];
        float2 c1 = g_csr[j + 1];
        float2 c2 = g_csr[j + 2];
        float2 c3 = g_csr[j + 3];
        int r0 = __float_as_int(c0.x);
        int r1 = __float_as_int(c1.x);
        int r2 = __float_as_int(c2.x);
        int r3 = __float_as_int(c3.x);
        float x00 = x[3 * r0 + 0], x01 = x[3 * r0 + 1], x02 = x[3 * r0 + 2];
        float x10 = x[3 * r1 + 0], x11 = x[3 * r1 + 1], x12 = x[3 * r1 + 2];
        float x20 = x[3 * r2 + 0], x21 = x[3 * r2 + 1], x22 = x[3 * r2 + 2];
        float x30 = x[3 * r3 + 0], x31 = x[3 * r3 + 1], x32 = x[3 * r3 + 2];
        a0 = fmaf(c0.y, x00, a0); a1 = fmaf(c0.y, x01, a1); a2 = fmaf(c0.y, x02, a2);
        a0 = fmaf(c1.y, x10, a0); a1 = fmaf(c1.y, x11, a1); a2 = fmaf(c1.y, x12, a2);
        a0 = fmaf(c2.y, x20, a0); a1 = fmaf(c2.y, x21, a1); a2 = fmaf(c2.y, x22, a2);
        a0 = fmaf(c3.y, x30, a0); a1 = fmaf(c3.y, x31, a1); a2 = fmaf(c3.y, x32, a2);
    }
    for (; j < end; j++) {
        float2 c = g_csr[j];
        int r = __float_as_int(c.x);
        a0 = fmaf(c.y, x[3 * r + 0], a0);
        a1 = fmaf(c.y, x[3 * r + 1], a1);
        a2 = fmaf(c.y, x[3 * r + 2], a2);
    }
#pragma unroll
    for (int c4 = 0; c4 < 25; c4++) {
        float4 o;
#pragma unroll
        for (int jj = 0; jj < 4; jj++) {
            int c = c4 * 4 + jj;
            float v = fmaf(a0, sW[c], fmaf(a1, sW[F1 + c], fmaf(a2, sW[2 * F1 + c], sW[3 * F1 + c])));
            (&o.x)[jj] = silu(v);
        }
        *(float4*)(g_h1 + (long)n * F1 + c4 * 4) = o;
    }
}

// ---------------- K7: agg1[n] = s*h1[n] + sum nrm*h1[row] (warp/node) -----
__global__ void k_agg1() {
    int n = (blockIdx.x * blockDim.x + threadIdx.x) >> 5;
    int lane = threadIdx.x & 31;
    if (n >= NN) return;
    bool act = lane < 25;
    int beg = g_offs[n], end = g_offs[n + 1];
    float di = g_dinv[n];
    float s = di * di;
    float4 acc = make_float4(0.f, 0.f, 0.f, 0.f);
    if (act) {
        float4 h = *(const float4*)(g_h1 + (long)n * F1 + lane * 4);
        acc.x = s * h.x; acc.y = s * h.y; acc.z = s * h.z; acc.w = s * h.w;
    }
    int j = beg;
    for (; j + 8 <= end; j += 8) {
        float2 cc[8];
        int rr[8];
#pragma unroll
        for (int q = 0; q < 8; q++) {
            cc[q] = g_csr[j + q];
            rr[q] = __float_as_int(cc[q].x);
        }
        if (act) {
            float4 hh[8];
#pragma unroll
            for (int q = 0; q < 8; q++)
                hh[q] = *(const float4*)(g_h1 + (long)rr[q] * F1 + lane * 4);
#pragma unroll
            for (int q = 0; q < 8; q++) {
                acc.x = fmaf(cc[q].y, hh[q].x, acc.x);
                acc.y = fmaf(cc[q].y, hh[q].y, acc.y);
                acc.z = fmaf(cc[q].y, hh[q].z, acc.z);
                acc.w = fmaf(cc[q].y, hh[q].w, acc.w);
            }
        }
    }
    for (; j + 2 <= end; j += 2) {
        float2 c0 = g_csr[j];
        float2 c1 = g_csr[j + 1];
        int r0 = __float_as_int(c0.x);
        int r1 = __float_as_int(c1.x);
        if (act) {
            float4 h0 = *(const float4*)(g_h1 + (long)r0 * F1 + lane * 4);
            float4 h1v = *(const float4*)(g_h1 + (long)r1 * F1 + lane * 4);
            acc.x = fmaf(c0.y, h0.x, acc.x); acc.y = fmaf(c0.y, h0.y, acc.y);
            acc.z = fmaf(c0.y, h0.z, acc.z); acc.w = fmaf(c0.y, h0.w, acc.w);
            acc.x = fmaf(c1.y, h1v.x, acc.x); acc.y = fmaf(c1.y, h1v.y, acc.y);
            acc.z = fmaf(c1.y, h1v.z, acc.z); acc.w = fmaf(c1.y, h1v.w, acc.w);
        }
    }
    if (j < end) {
        float2 c0 = g_csr[j];
        int r0 = __float_as_int(c0.x);
        if (act) {
            float4 h0 = *(const float4*)(g_h1 + (long)r0 * F1 + lane * 4);
            acc.x = fmaf(c0.y, h0.x, acc.x); acc.y = fmaf(c0.y, h0.y, acc.y);
            acc.z = fmaf(c0.y, h0.z, acc.z); acc.w = fmaf(c0.y, h0.w, acc.w);
        }
    }
    if (act)
        *(float4*)(g_agg1 + (long)n * F1 + lane * 4) = acc;
}

// ---------------- K8: 3xTF32 GEMM, A staged once, reg-pool epilogue -------
// grid = ceil(NN/64) (1-D), 128 threads (4 warps, one m16 band each).
// A-tile loaded once into smem; internal loop over 5 col-blocks of 40.
// Pooling done from mma accumulators: shfl_xor butterfly over the 8 r-lanes
// when all 16 warp rows share one graph (common), else per-lane atomics.
#define BM 64
#define BN 40
#define KP 104
#define ASTRIDE 108

__global__ void k_gemm2(const float* __restrict__ W2, const float* __restrict__ b2,
                        const int* __restrict__ batch) {
    __shared__ float As[BM * ASTRIDE];   // [m][k] fp32 (lives whole kernel)
    __shared__ float Bs[KP * BN];        // [k][c] fp32 (per col-block)
    __shared__ int sBatch[BM];
    int tid = threadIdx.x;
    int lane = tid & 31;
    int wid = tid >> 5;
    int n0 = blockIdx.x * BM;

    // load A tile once
    for (int t = tid; t < BM * 25; t += 128) {
        int m = t / 25, k4 = t % 25;
        int n = n0 + m;
        float4 v = make_float4(0.f, 0.f, 0.f, 0.f);
        if (n < NN) v = *(const float4*)(g_agg1 + (long)n * F1 + k4 * 4);
        *(float4*)(As + m * ASTRIDE + k4 * 4) = v;
    }
    for (int t = tid; t < BM * 8; t += 128)
        As[(t >> 3) * ASTRIDE + 100 + (t & 7)] = 0.f;
    // zero K padding rows of Bs once (never overwritten by col-block loads)
    for (int t = tid; t < 4 * BN; t += 128)
        Bs[(100 + t / BN) * BN + (t % BN)] = 0.f;
    if (tid < BM) {
        int n = n0 + tid;
        sBatch[tid] = (n < NN) ? batch[n] : -1;
    }
    __syncthreads();

    int base = wid * 16;
    int r = lane >> 2;
    int c = lane & 3;

    // per-warp graph uniformity over its 16 rows
    int g0 = sBatch[base + r];
    int g1 = sBatch[base + r + 8];
    int gref = __shfl_sync(0xffffffffu, g0, 0);
    bool uni = __all_sync(0xffffffffu, g0 == gref && g1 == gref) && (gref >= 0);

#pragma unroll 1
    for (int cbi = 0; cbi < 5; cbi++) {
        int cb = cbi * BN;
        // load Bs for this col-block (W2 80KB, L2-hot)
        for (int t = tid; t < F1 * 10; t += 128) {
            int k = t / 10, c4 = t % 10;
            *(float4*)(Bs + k * BN + c4 * 4) = *(const float4*)(W2 + k * F2 + cb + c4 * 4);
        }
        __syncthreads();

        float acc[5][4] = {};
#pragma unroll
        for (int ks = 0; ks < 13; ks++) {
            int kb = ks * 8;
            float fa0 = As[(base + r) * ASTRIDE + kb + c];
            float fa1 = As[(base + r + 8) * ASTRIDE + kb + c];
            float fa2 = As[(base + r) * ASTRIDE + kb + c + 4];
            float fa3 = As[(base + r + 8) * ASTRIDE + kb + c + 4];
            unsigned ah0, al0, ah1, al1, ah2, al2, ah3, al3;
            split_tf32(fa0, ah0, al0);
            split_tf32(fa1, ah1, al1);
            split_tf32(fa2, ah2, al2);
            split_tf32(fa3, ah3, al3);
#pragma unroll
            for (int t = 0; t < 5; t++) {
                float fb0 = Bs[(kb + c) * BN + t * 8 + r];
                float fb1 = Bs[(kb + 4 + c) * BN + t * 8 + r];
                unsigned bh0, bl0, bh1, bl1;
                split_tf32(fb0, bh0, bl0);
                split_tf32(fb1, bh1, bl1);
                mma_tf32(acc[t][0], acc[t][1], acc[t][2], acc[t][3],
                         ah0, ah1, ah2, ah3, bl0, bl1);
                mma_tf32(acc[t][0], acc[t][1], acc[t][2], acc[t][3],
                         al0, al1, al2, al3, bh0, bh1);
                mma_tf32(acc[t][0], acc[t][1], acc[t][2], acc[t][3],
                         ah0, ah1, ah2, ah3, bh0, bh1);
            }
        }

        // epilogue: silu + pool straight from registers
#pragma unroll
        for (int t = 0; t < 5; t++) {
            int col = cb + t * 8 + c * 2;
            float bx = b2[col];
            float by = b2[col + 1];
            float v00 = silu(acc[t][0] + bx);   // (base+r,   col)
            float v01 = silu(acc[t][1] + by);   // (base+r,   col+1)
            float v10 = silu(acc[t][2] + bx);   // (base+r+8, col)
            float v11 = silu(acc[t][3] + by);   // (base+r+8, col+1)
            if (uni) {
                float s0 = v00 + v10;
                float s1 = v01 + v11;
                s0 += __shfl_xor_sync(0xffffffffu, s0, 4);
                s0 += __shfl_xor_sync(0xffffffffu, s0, 8);
                s0 += __shfl_xor_sync(0xffffffffu, s0, 16);
                s1 += __shfl_xor_sync(0xffffffffu, s1, 4);
                s1 += __shfl_xor_sync(0xffffffffu, s1, 8);
                s1 += __shfl_xor_sync(0xffffffffu, s1, 16);
                if (lane < 4) {
                    atomicAdd(&g_sums[gref * F2 + col], s0);
                    atomicAdd(&g_sums[gref * F2 + col + 1], s1);
                }
            } else {
                if (g0 >= 0) {
                    atomicAdd(&g_sums[g0 * F2 + col], v00);
                    atomicAdd(&g_sums[g0 * F2 + col + 1], v01);
                }
                if (g1 >= 0) {
                    atomicAdd(&g_sums[g1 * F2 + col], v10);
                    atomicAdd(&g_sums[g1 * F2 + col + 1], v11);
                }
            }
        }
        __syncthreads();   // Bs reuse guard for next col-block
    }
}

// ---------------- K9: head: silu(pooled@Wl1+bl1)@Wl2+bl2 ------------------
__global__ void k_head(const float* __restrict__ Wl1, const float* __restrict__ bl1,
                       const float* __restrict__ Wl2, const float* __restrict__ bl2,
                       float* __restrict__ out) {
    __shared__ float sp[F2];
    __shared__ float sh[F1];
    int g = blockIdx.x;
    int tid = threadIdx.x;
    float cnt = fmaxf(g_cnt[g], 1.0f);
    for (int c = tid; c < F2; c += blockDim.x)
        sp[c] = g_sums[g * F2 + c] / cnt;
    __syncthreads();
    if (tid < F1) {
        float acc = bl1[tid];
        for (int c = 0; c < F2; c++)
            acc = fmaf(sp[c], Wl1[c * F1 + tid], acc);
        sh[tid] = silu(acc);
    }
    __syncthreads();
    if (tid == 0) {
        float s = bl2[0];
        for (int j = 0; j < F1; j++)
            s = fmaf(sh[j], Wl2[j], s);
        out[g] = s;
    }
}

// ---------------- launch ---------------------------------------------------
extern "C" void kernel_launch(void* const* d_in, const int* in_sizes, int n_in,
                              void* d_out, int out_size) {
    const float* x   = (const float*)d_in[0];
    const float* ea  = (const float*)d_in[1];
    const float* W1  = (const float*)d_in[2];
    const float* b1  = (const float*)d_in[3];
    const float* W2  = (const float*)d_in[4];
    const float* b2  = (const float*)d_in[5];
    const float* Wl1 = (const float*)d_in[6];
    const float* bl1 = (const float*)d_in[7];
    const float* Wl2 = (const float*)d_in[8];
    const float* bl2 = (const float*)d_in[9];
    const int*   ei  = (const int*)d_in[10];
    const int*   bat = (const int*)d_in[11];
    float* out = (float*)d_out;

    k_init<<<(NN + 255) / 256, 256>>>();
    k_deg<<<(NE + 255) / 256, 256>>>(ei, ea);
    k_dinv<<<(NN + 255) / 256, 256>>>(bat);
    k_scan1<<<98, 256>>>();
    k_scan2<<<1, 128>>>();
    k_scan3<<<(NN + 255) / 256, 256>>>();
    k_build<<<(NE + 255) / 256, 256>>>(ei, ea);
    k_aggXh1<<<(NN + 255) / 256, 256>>>(x, W1, b1);
    k_agg1<<<(NN * 32 + 255) / 256, 256>>>();
    k_gemm2<<<(NN + BM - 1) / BM, 128>>>(W2, b2, bat);
    k_head<<<NG, 128>>>(Wl1, bl1, Wl2, bl2, out);
}

// round 15
// speedup vs baseline: 1.0080x; 1.0059x over previous
#include <cuda_runtime.h>
#include <math.h>

#define NN 100000
#define NE 1600000
#define NG 64
#define F1 100
#define F2 200

// ---------------- scratch (static device globals; no allocation) ----------
__device__ float2 g_pack[NN];          // (deg_sum, deg_count) packed for v2 red
__device__ float  g_dinv[NN];          // rsqrt(deg)
__device__ int    g_cdeg[NN];          // in-degree counts (for CSR)
__device__ int    g_offs[NN + 1];      // CSR offsets
__device__ int    g_fill[NN];          // CSR fill cursors
__device__ int    g_bsum[128];         // scan block sums
__device__ float2 g_csr[NE];           // (row as int bits, norm)
__device__ float  g_h1[NN * F1];       // silu((A@x) @ W1 + b1)
__device__ float  g_agg1[NN * F1];     // A_norm @ h1
__device__ float  g_sums[NG * F2];     // pooled sums
__device__ float  g_cnt[NG];           // pooled counts

__device__ __forceinline__ float silu(float v) {
    return v / (1.0f + __expf(-v));
}

__device__ __forceinline__ unsigned f2tf32(float v) {
    unsigned r;
    asm("cvt.rna.tf32.f32 %0, %1;" : "=r"(r) : "f"(v));
    return r;
}

__device__ __forceinline__ void split_tf32(float v, unsigned& hi, unsigned& lo) {
    hi = f2tf32(v);
    lo = f2tf32(v - __uint_as_float(hi));
}

__device__ __forceinline__ void mma_tf32(float& d0, float& d1, float& d2, float& d3,
                                         unsigned a0, unsigned a1, unsigned a2, unsigned a3,
                                         unsigned b0, unsigned b1) {
    asm volatile("mma.sync.aligned.m16n8k8.row.col.f32.tf32.tf32.f32 "
                 "{%0,%1,%2,%3}, {%4,%5,%6,%7}, {%8,%9}, {%0,%1,%2,%3};"
                 : "+f"(d0), "+f"(d1), "+f"(d2), "+f"(d3)
                 : "r"(a0), "r"(a1), "r"(a2), "r"(a3), "r"(b0), "r"(b1));
}

__device__ __forceinline__ void red_add_v2(float2* p, float a, float b) {
    asm volatile("red.global.add.v2.f32 [%0], {%1,%2};"
                 :: "l"(p), "f"(a), "f"(b) : "memory");
}

// ---------------- K1: init pack (self-loop: deg=1, cnt=0), zero pooled ----
__global__ void k_init() {
    int i = blockIdx.x * blockDim.x + threadIdx.x;
    if (i < NN) g_pack[i] = make_float2(1.0f, 0.0f);
    if (i < NG * F2) g_sums[i] = 0.0f;
    if (i < NG) g_cnt[i] = 0.0f;
}

// ---------------- K2: packed deg/count reduction (1 atomic per edge) ------
__global__ void k_deg(const int* __restrict__ ei, const float* __restrict__ w) {
    int e = blockIdx.x * blockDim.x + threadIdx.x;
    if (e >= NE) return;
    int col = ei[NE + e];
    red_add_v2(&g_pack[col], w[e], 1.0f);
}

// ---------------- K3: dinv = rsqrt(deg); cdeg; graph counts ---------------
__global__ void k_dinv(const int* __restrict__ batch) {
    int n = blockIdx.x * blockDim.x + threadIdx.x;
    bool valid = n < NN;
    if (valid) {
        float2 p = g_pack[n];
        g_dinv[n] = rsqrtf(p.x);          // deg >= 1 (self loop)
        g_cdeg[n] = (int)p.y;             // counts exact in float
    }
    int g = valid ? batch[n] : -1;
    unsigned m = __match_any_sync(0xffffffffu, g);
    int lane = threadIdx.x & 31;
    int leader = __ffs(m) - 1;
    if (valid && lane == leader)
        atomicAdd(&g_cnt[g], (float)__popc(m));
}

// ---------------- scan: exclusive prefix sum of cdeg -> offs --------------
__global__ void k_scan1() {
    __shared__ int warp_s[8];
    int b = blockIdx.x, t = threadIdx.x;
    int base = b * 1024 + t * 4;
    int v0 = 0, v1 = 0, v2 = 0, v3 = 0;
    if (base + 0 < NN) v0 = g_cdeg[base + 0];
    if (base + 1 < NN) v1 = g_cdeg[base + 1];
    if (base + 2 < NN) v2 = g_cdeg[base + 2];
    if (base + 3 < NN) v3 = g_cdeg[base + 3];
    int s = v0 + v1 + v2 + v3;
    int lane = t & 31, wid = t >> 5;
    int ps = s;
#pragma unroll
    for (int o = 1; o < 32; o <<= 1) {
        int u = __shfl_up_sync(0xffffffffu, ps, o);
        if (lane >= o) ps += u;
    }
    if (lane == 31) warp_s[wid] = ps;
    __syncthreads();
    if (t < 8) {
        int ws = warp_s[t];
        int pw = ws;
#pragma unroll
        for (int o = 1; o < 8; o <<= 1) {
            int u = __shfl_up_sync(0xffu, pw, o);
            if (t >= o) pw += u;
        }
        warp_s[t] = pw - ws;
    }
    __syncthreads();
    int ex = ps - s + warp_s[wid];
    int run = ex;
    if (base + 0 < NN) g_offs[base + 0] = run; run += v0;
    if (base + 1 < NN) g_offs[base + 1] = run; run += v1;
    if (base + 2 < NN) g_offs[base + 2] = run; run += v2;
    if (base + 3 < NN) g_offs[base + 3] = run;
    if (t == 255) g_bsum[b] = ex + s;
}

__global__ void k_scan2() {
    __shared__ int sh[4];
    int t = threadIdx.x;
    int v = (t < 98) ? g_bsum[t] : 0;
    int lane = t & 31, wid = t >> 5;
    int ps = v;
#pragma unroll
    for (int o = 1; o < 32; o <<= 1) {
        int u = __shfl_up_sync(0xffffffffu, ps, o);
        if (lane >= o) ps += u;
    }
    if (lane == 31) sh[wid] = ps;
    __syncthreads();
    if (t < 4) {
        int ws = sh[t];
        int pw = ws;
#pragma unroll
        for (int o = 1; o < 4; o <<= 1) {
            int u = __shfl_up_sync(0xfu, pw, o);
            if (t >= o) pw += u;
        }
        sh[t] = pw - ws;
    }
    __syncthreads();
    if (t < 98) g_bsum[t] = ps - v + sh[wid];
}

__global__ void k_scan3() {
    int i = blockIdx.x * blockDim.x + threadIdx.x;
    if (i < NN) {
        int o = g_offs[i] + g_bsum[i >> 10];
        g_offs[i] = o;
        g_fill[i] = o;
    }
    if (i == 0) g_offs[NN] = NE;
}

// ---------------- K5: build CSR (row, norm) per target node ---------------
__global__ void k_build(const int* __restrict__ ei, const float* __restrict__ w) {
    int e = blockIdx.x * blockDim.x + threadIdx.x;
    if (e >= NE) return;
    int row = ei[e];
    int col = ei[NE + e];
    float nm = g_dinv[row] * w[e] * g_dinv[col];
    int pos = atomicAdd(&g_fill[col], 1);
    g_csr[pos] = make_float2(__int_as_float(row), nm);
}

// ---------------- K6: fused aggX + h1 -------------------------------------
__global__ void k_aggXh1(const float* __restrict__ x,
                         const float* __restrict__ W1, const float* __restrict__ b1) {
    __shared__ float sW[4 * F1];
    for (int t = threadIdx.x; t < 4 * F1; t += blockDim.x)
        sW[t] = (t < 3 * F1) ? W1[t] : b1[t - 3 * F1];
    __syncthreads();
    int n = blockIdx.x * blockDim.x + threadIdx.x;
    if (n >= NN) return;
    float di = g_dinv[n];
    float s = di * di;
    float a0 = s * x[3 * n + 0];
    float a1 = s * x[3 * n + 1];
    float a2 = s * x[3 * n + 2];
    int beg = g_offs[n], end = g_offs[n + 1];
    int j = beg;
    for (; j + 4 <= end; j += 4) {
        float2 c0 = g_csr[j + 0];
        float2 c1 = g_csr[j + 1];
        float2 c2 = g_csr[j + 2];
        float2 c3 = g_csr[j + 3];
        int r0 = __float_as_int(c0.x);
        int r1 = __float_as_int(c1.x);
        int r2 = __float_as_int(c2.x);
        int r3 = __float_as_int(c3.x);
        float x00 = x[3 * r0 + 0], x01 = x[3 * r0 + 1], x02 = x[3 * r0 + 2];
        float x10 = x[3 * r1 + 0], x11 = x[3 * r1 + 1], x12 = x[3 * r1 + 2];
        float x20 = x[3 * r2 + 0], x21 = x[3 * r2 + 1], x22 = x[3 * r2 + 2];
        float x30 = x[3 * r3 + 0], x31 = x[3 * r3 + 1], x32 = x[3 * r3 + 2];
        a0 = fmaf(c0.y, x00, a0); a1 = fmaf(c0.y, x01, a1); a2 = fmaf(c0.y, x02, a2);
        a0 = fmaf(c1.y, x10, a0); a1 = fmaf(c1.y, x11, a1); a2 = fmaf(c1.y, x12, a2);
        a0 = fmaf(c2.y, x20, a0); a1 = fmaf(c2.y, x21, a1); a2 = fmaf(c2.y, x22, a2);
        a0 = fmaf(c3.y, x30, a0); a1 = fmaf(c3.y, x31, a1); a2 = fmaf(c3.y, x32, a2);
    }
    for (; j < end; j++) {
        float2 c = g_csr[j];
        int r = __float_as_int(c.x);
        a0 = fmaf(c.y, x[3 * r + 0], a0);
        a1 = fmaf(c.y, x[3 * r + 1], a1);
        a2 = fmaf(c.y, x[3 * r + 2], a2);
    }
#pragma unroll
    for (int c4 = 0; c4 < 25; c4++) {
        float4 o;
#pragma unroll
        for (int jj = 0; jj < 4; jj++) {
            int c = c4 * 4 + jj;
            float v = fmaf(a0, sW[c], fmaf(a1, sW[F1 + c], fmaf(a2, sW[2 * F1 + c], sW[3 * F1 + c])));
            (&o.x)[jj] = silu(v);
        }
        *(float4*)(g_h1 + (long)n * F1 + c4 * 4) = o;
    }
}

// ---------------- K7: agg1[n] = s*h1[n] + sum nrm*h1[row] (warp/node) -----
__global__ void k_agg1() {
    int n = (blockIdx.x * blockDim.x + threadIdx.x) >> 5;
    int lane = threadIdx.x & 31;
    if (n >= NN) return;
    bool act = lane < 25;
    int beg = g_offs[n], end = g_offs[n + 1];
    float di = g_dinv[n];
    float s = di * di;
    float4 acc = make_float4(0.f, 0.f, 0.f, 0.f);
    if (act) {
        float4 h = *(const float4*)(g_h1 + (long)n * F1 + lane * 4);
        acc.x = s * h.x; acc.y = s * h.y; acc.z = s * h.z; acc.w = s * h.w;
    }
    int j = beg;
    for (; j + 8 <= end; j += 8) {
        float2 cc[8];
        int rr[8];
#pragma unroll
        for (int q = 0; q < 8; q++) {
            cc[q] = g_csr[j + q];
            rr[q] = __float_as_int(cc[q].x);
        }
        if (act) {
            float4 hh[8];
#pragma unroll
            for (int q = 0; q < 8; q++)
                hh[q] = *(const float4*)(g_h1 + (long)rr[q] * F1 + lane * 4);
#pragma unroll
            for (int q = 0; q < 8; q++) {
                acc.x = fmaf(cc[q].y, hh[q].x, acc.x);
                acc.y = fmaf(cc[q].y, hh[q].y, acc.y);
                acc.z = fmaf(cc[q].y, hh[q].z, acc.z);
                acc.w = fmaf(cc[q].y, hh[q].w, acc.w);
            }
        }
    }
    for (; j + 2 <= end; j += 2) {
        float2 c0 = g_csr[j];
        float2 c1 = g_csr[j + 1];
        int r0 = __float_as_int(c0.x);
        int r1 = __float_as_int(c1.x);
        if (act) {
            float4 h0 = *(const float4*)(g_h1 + (long)r0 * F1 + lane * 4);
            float4 h1v = *(const float4*)(g_h1 + (long)r1 * F1 + lane * 4);
            acc.x = fmaf(c0.y, h0.x, acc.x); acc.y = fmaf(c0.y, h0.y, acc.y);
            acc.z = fmaf(c0.y, h0.z, acc.z); acc.w = fmaf(c0.y, h0.w, acc.w);
            acc.x = fmaf(c1.y, h1v.x, acc.x); acc.y = fmaf(c1.y, h1v.y, acc.y);
            acc.z = fmaf(c1.y, h1v.z, acc.z); acc.w = fmaf(c1.y, h1v.w, acc.w);
        }
    }
    if (j < end) {
        float2 c0 = g_csr[j];
        int r0 = __float_as_int(c0.x);
        if (act) {
            float4 h0 = *(const float4*)(g_h1 + (long)r0 * F1 + lane * 4);
            acc.x = fmaf(c0.y, h0.x, acc.x); acc.y = fmaf(c0.y, h0.y, acc.y);
            acc.z = fmaf(c0.y, h0.z, acc.z); acc.w = fmaf(c0.y, h0.w, acc.w);
        }
    }
    if (act)
        *(float4*)(g_agg1 + (long)n * F1 + lane * 4) = acc;
}

// ---------------- K8: 3xTF32 GEMM, A staged once, reg-pool epilogue -------
// grid = ceil(NN/64) (1-D), 128 threads (4 warps, one m16 band each).
// A-tile loaded once into smem; internal loop over 5 col-blocks of 40.
// Pooling done from mma accumulators: shfl_xor butterfly over the 8 r-lanes
// when all 16 warp rows share one graph (common), else per-lane atomics.
#define BM 64
#define BN 40
#define KP 104
#define ASTRIDE 108

__global__ void k_gemm2(const float* __restrict__ W2, const float* __restrict__ b2,
                        const int* __restrict__ batch) {
    __shared__ float As[BM * ASTRIDE];   // [m][k] fp32 (lives whole kernel)
    __shared__ float Bs[KP * BN];        // [k][c] fp32 (per col-block)
    __shared__ int sBatch[BM];
    int tid = threadIdx.x;
    int lane = tid & 31;
    int wid = tid >> 5;
    int n0 = blockIdx.x * BM;

    // load A tile once
    for (int t = tid; t < BM * 25; t += 128) {
        int m = t / 25, k4 = t % 25;
        int n = n0 + m;
        float4 v = make_float4(0.f, 0.f, 0.f, 0.f);
        if (n < NN) v = *(const float4*)(g_agg1 + (long)n * F1 + k4 * 4);
        *(float4*)(As + m * ASTRIDE + k4 * 4) = v;
    }
    for (int t = tid; t < BM * 8; t += 128)
        As[(t >> 3) * ASTRIDE + 100 + (t & 7)] = 0.f;
    // zero K padding rows of Bs once (never overwritten by col-block loads)
    for (int t = tid; t < 4 * BN; t += 128)
        Bs[(100 + t / BN) * BN + (t % BN)] = 0.f;
    if (tid < BM) {
        int n = n0 + tid;
        sBatch[tid] = (n < NN) ? batch[n] : -1;
    }
    __syncthreads();

    int base = wid * 16;
    int r = lane >> 2;
    int c = lane & 3;

    // per-warp graph uniformity over its 16 rows
    int g0 = sBatch[base + r];
    int g1 = sBatch[base + r + 8];
    int gref = __shfl_sync(0xffffffffu, g0, 0);
    bool uni = __all_sync(0xffffffffu, g0 == gref && g1 == gref) && (gref >= 0);

#pragma unroll 1
    for (int cbi = 0; cbi < 5; cbi++) {
        int cb = cbi * BN;
        // load Bs for this col-block (W2 80KB, L2-hot)
        for (int t = tid; t < F1 * 10; t += 128) {
            int k = t / 10, c4 = t % 10;
            *(float4*)(Bs + k * BN + c4 * 4) = *(const float4*)(W2 + k * F2 + cb + c4 * 4);
        }
        __syncthreads();

        float acc[5][4] = {};
#pragma unroll
        for (int ks = 0; ks < 13; ks++) {
            int kb = ks * 8;
            float fa0 = As[(base + r) * ASTRIDE + kb + c];
            float fa1 = As[(base + r + 8) * ASTRIDE + kb + c];
            float fa2 = As[(base + r) * ASTRIDE + kb + c + 4];
            float fa3 = As[(base + r + 8) * ASTRIDE + kb + c + 4];
            unsigned ah0, al0, ah1, al1, ah2, al2, ah3, al3;
            split_tf32(fa0, ah0, al0);
            split_tf32(fa1, ah1, al1);
            split_tf32(fa2, ah2, al2);
            split_tf32(fa3, ah3, al3);
#pragma unroll
            for (int t = 0; t < 5; t++) {
                float fb0 = Bs[(kb + c) * BN + t * 8 + r];
                float fb1 = Bs[(kb + 4 + c) * BN + t * 8 + r];
                unsigned bh0, bl0, bh1, bl1;
                split_tf32(fb0, bh0, bl0);
                split_tf32(fb1, bh1, bl1);
                mma_tf32(acc[t][0], acc[t][1], acc[t][2], acc[t][3],
                         ah0, ah1, ah2, ah3, bl0, bl1);
                mma_tf32(acc[t][0], acc[t][1], acc[t][2], acc[t][3],
                         al0, al1, al2, al3, bh0, bh1);
                mma_tf32(acc[t][0], acc[t][1], acc[t][2], acc[t][3],
                         ah0, ah1, ah2, ah3, bh0, bh1);
            }
        }

        // epilogue: silu + pool straight from registers
#pragma unroll
        for (int t = 0; t < 5; t++) {
            int col = cb + t * 8 + c * 2;
            float bx = b2[col];
            float by = b2[col + 1];
            float v00 = silu(acc[t][0] + bx);   // (base+r,   col)
            float v01 = silu(acc[t][1] + by);   // (base+r,   col+1)
            float v10 = silu(acc[t][2] + bx);   // (base+r+8, col)
            float v11 = silu(acc[t][3] + by);   // (base+r+8, col+1)
            if (uni) {
                float s0 = v00 + v10;
                float s1 = v01 + v11;
                s0 += __shfl_xor_sync(0xffffffffu, s0, 4);
                s0 += __shfl_xor_sync(0xffffffffu, s0, 8);
                s0 += __shfl_xor_sync(0xffffffffu, s0, 16);
                s1 += __shfl_xor_sync(0xffffffffu, s1, 4);
                s1 += __shfl_xor_sync(0xffffffffu, s1, 8);
                s1 += __shfl_xor_sync(0xffffffffu, s1, 16);
                if (lane < 4) {
                    atomicAdd(&g_sums[gref * F2 + col], s0);
                    atomicAdd(&g_sums[gref * F2 + col + 1], s1);
                }
            } else {
                if (g0 >= 0) {
                    atomicAdd(&g_sums[g0 * F2 + col], v00);
                    atomicAdd(&g_sums[g0 * F2 + col + 1], v01);
                }
                if (g1 >= 0) {
                    atomicAdd(&g_sums[g1 * F2 + col], v10);
                    atomicAdd(&g_sums[g1 * F2 + col + 1], v11);
                }
            }
        }
        __syncthreads();   // Bs reuse guard for next col-block
    }
}

// ---------------- K9: head: silu(pooled@Wl1+bl1)@Wl2+bl2 ------------------
__global__ void k_head(const float* __restrict__ Wl1, const float* __restrict__ bl1,
                       const float* __restrict__ Wl2, const float* __restrict__ bl2,
                       float* __restrict__ out) {
    __shared__ float sp[F2];
    __shared__ float sh[F1];
    int g = blockIdx.x;
    int tid = threadIdx.x;
    float cnt = fmaxf(g_cnt[g], 1.0f);
    for (int c = tid; c < F2; c += blockDim.x)
        sp[c] = g_sums[g * F2 + c] / cnt;
    __syncthreads();
    if (tid < F1) {
        float acc = bl1[tid];
        for (int c = 0; c < F2; c++)
            acc = fmaf(sp[c], Wl1[c * F1 + tid], acc);
        sh[tid] = silu(acc);
    }
    __syncthreads();
    if (tid == 0) {
        float s = bl2[0];
        for (int j = 0; j < F1; j++)
            s = fmaf(sh[j], Wl2[j], s);
        out[g] = s;
    }
}

// ---------------- launch ---------------------------------------------------
extern "C" void kernel_launch(void* const* d_in, const int* in_sizes, int n_in,
                              void* d_out, int out_size) {
    const float* x   = (const float*)d_in[0];
    const float* ea  = (const float*)d_in[1];
    const float* W1  = (const float*)d_in[2];
    const float* b1  = (const float*)d_in[3];
    const float* W2  = (const float*)d_in[4];
    const float* b2  = (const float*)d_in[5];
    const float* Wl1 = (const float*)d_in[6];
    const float* bl1 = (const float*)d_in[7];
    const float* Wl2 = (const float*)d_in[8];
    const float* bl2 = (const float*)d_in[9];
    const int*   ei  = (const int*)d_in[10];
    const int*   bat = (const int*)d_in[11];
    float* out = (float*)d_out;

    k_init<<<(NN + 255) / 256, 256>>>();
    k_deg<<<(NE + 255) / 256, 256>>>(ei, ea);
    k_dinv<<<(NN + 255) / 256, 256>>>(bat);
    k_scan1<<<98, 256>>>();
    k_scan2<<<1, 128>>>();
    k_scan3<<<(NN + 255) / 256, 256>>>();
    k_build<<<(NE + 255) / 256, 256>>>(ei, ea);
    k_aggXh1<<<(NN + 255) / 256, 256>>>(x, W1, b1);
    k_agg1<<<(NN * 32 + 255) / 256, 256>>>();
    k_gemm2<<<(NN + BM - 1) / BM, 128>>>(W2, b2, bat);
    k_head<<<NG, 128>>>(Wl1, bl1, Wl2, bl2, out);
}